// round 2
// baseline (speedup 1.0000x reference)
#include <cuda_runtime.h>
#include <math.h>

#define BB 64
#define FF 128
#define TT 1024
#define HH 512
#define GG 2048   // 4*H
#define NBLK 128

typedef unsigned long long ull;

// ---------------- scratch (device globals; no allocation allowed) ----------------
__device__ float g_xTt [(size_t)TT * BB * FF];   // (T,B,F)   32 MB
__device__ float g_xg0 [(size_t)TT * BB * GG];   // (T*B,4H) 512 MB
__device__ float g_out0[(size_t)TT * BB * HH];   // (T,B,H)  128 MB
__device__ float g_xg1 [(size_t)TT * BB * GG];   // (T*B,4H) 512 MB
__device__ float g_out1[(size_t)TT * BB * HH];   // (T,B,H)  128 MB
__device__ float g_zero[BB * HH];                // stays zero forever
__device__ unsigned g_flag0[NBLK * 8];
__device__ unsigned g_flag1[NBLK * 8];

// ---------------- f32x2 packed-FMA helpers ----------------
__device__ __forceinline__ void fma2(ull& acc, ull a, ull b) {
    asm("fma.rn.f32x2 %0, %1, %2, %0;" : "+l"(acc) : "l"(a), "l"(b));
}
__device__ __forceinline__ ull dup2(float x) {
    ull r; asm("mov.b64 %0, {%1, %1};" : "=l"(r) : "f"(x)); return r;
}
__device__ __forceinline__ float2 unp(ull v) {
    float2 r; asm("mov.b64 {%0, %1}, %2;" : "=f"(r.x), "=f"(r.y) : "l"(v)); return r;
}
__device__ __forceinline__ float sigf(float x) { return 1.f / (1.f + __expf(-x)); }

// ---------------- reset barrier flags ----------------
__global__ void reset_kernel() {
    int i = threadIdx.x;
    if (i < NBLK) { g_flag0[i * 8] = 0u; g_flag1[i * 8] = 0u; }
}

// ---------------- transpose x (B,F,T) -> (T,B,F) ----------------
__global__ void transpose_x_kernel(const float* __restrict__ x) {
    __shared__ float tile[32][33];
    int b  = blockIdx.z;
    int t0 = blockIdx.x * 32;
    int f0 = blockIdx.y * 32;
    for (int i = threadIdx.y; i < 32; i += 8)
        tile[i][threadIdx.x] = x[(size_t)b * FF * TT + (size_t)(f0 + i) * TT + t0 + threadIdx.x];
    __syncthreads();
    for (int i = threadIdx.y; i < 32; i += 8)
        g_xTt[(size_t)(t0 + i) * BB * FF + (size_t)b * FF + f0 + threadIdx.x] = tile[threadIdx.x][i];
}

// ---------------- big GEMM: C(M,2048) = A(M,K) @ W(2048,K)^T + bih + bhh ----------------
// 64x64 block tile, KC=16, 256 threads, 4x4 per thread, f32x2 accumulation,
// double-buffered smem with register prefetch.
template <int K>
__global__ __launch_bounds__(256, 2)
void gemm_gates(const float* __restrict__ A, const float* __restrict__ W,
                const float* __restrict__ bih, const float* __restrict__ bhh,
                float* __restrict__ C) {
    __shared__ __align__(16) float As[2][16 * 68];
    __shared__ __align__(16) float Bs[2][16 * 68];
    const int tid = threadIdx.x, tx = tid & 15, ty = tid >> 4;
    const int n0 = blockIdx.x * 64, m0 = blockIdx.y * 64;
    const int srow = tid >> 2, skc = (tid & 3) * 4;

    const float* Ap = A + (size_t)(m0 + srow) * K + skc;
    const float* Wp = W + (size_t)(n0 + srow) * K + skc;
    float4 ra = *(const float4*)Ap;
    float4 rb = *(const float4*)Wp;

    ull acc[4][2];
    #pragma unroll
    for (int n = 0; n < 4; ++n) { acc[n][0] = 0ull; acc[n][1] = 0ull; }

    const int KT = K / 16;
    #pragma unroll 1
    for (int kt = 0; kt < KT; ++kt) {
        const int buf = kt & 1;
        float* Ab = &As[buf][0];
        float* Bb = &Bs[buf][0];
        Ab[(skc + 0) * 68 + srow] = ra.x; Ab[(skc + 1) * 68 + srow] = ra.y;
        Ab[(skc + 2) * 68 + srow] = ra.z; Ab[(skc + 3) * 68 + srow] = ra.w;
        Bb[(skc + 0) * 68 + srow] = rb.x; Bb[(skc + 1) * 68 + srow] = rb.y;
        Bb[(skc + 2) * 68 + srow] = rb.z; Bb[(skc + 3) * 68 + srow] = rb.w;
        if (kt + 1 < KT) {
            ra = *(const float4*)(Ap + (kt + 1) * 16);
            rb = *(const float4*)(Wp + (kt + 1) * 16);
        }
        __syncthreads();
        #pragma unroll
        for (int k = 0; k < 16; ++k) {
            ulonglong2 a = *(const ulonglong2*)&Ab[k * 68 + 4 * ty];
            float4 b = *(const float4*)&Bb[k * 68 + 4 * tx];
            ull b0 = dup2(b.x), b1 = dup2(b.y), b2 = dup2(b.z), b3 = dup2(b.w);
            fma2(acc[0][0], a.x, b0); fma2(acc[0][1], a.y, b0);
            fma2(acc[1][0], a.x, b1); fma2(acc[1][1], a.y, b1);
            fma2(acc[2][0], a.x, b2); fma2(acc[2][1], a.y, b2);
            fma2(acc[3][0], a.x, b3); fma2(acc[3][1], a.y, b3);
        }
        __syncthreads();
    }

    float bv[4];
    #pragma unroll
    for (int u = 0; u < 4; ++u)
        bv[u] = bih[n0 + 4 * tx + u] + bhh[n0 + 4 * tx + u];

    #pragma unroll
    for (int h = 0; h < 2; ++h) {
        float2 p0 = unp(acc[0][h]), p1 = unp(acc[1][h]);
        float2 p2 = unp(acc[2][h]), p3 = unp(acc[3][h]);
        size_t r0 = (size_t)(m0 + 4 * ty + 2 * h) * GG + n0 + 4 * tx;
        *(float4*)&C[r0]      = make_float4(p0.x + bv[0], p1.x + bv[1], p2.x + bv[2], p3.x + bv[3]);
        *(float4*)&C[r0 + GG] = make_float4(p0.y + bv[0], p1.y + bv[1], p2.y + bv[2], p3.y + bv[3]);
    }
}

// ---------------- persistent LSTM recurrence ----------------
// 128 blocks (co-resident), block blk owns h-cols [4*blk, 4*blk+4).
// Whh slice (16 rows x 512) cached in SMEM for all steps. Per step:
// gates(64x16) = h(64,512) @ Whh_slice^T (f32x2), + precomputed xg[t], cell, h-write, grid barrier.
__global__ __launch_bounds__(256)
void lstm_rec(const float* __restrict__ xg, const float* __restrict__ Whh,
              float* __restrict__ seqout, float* __restrict__ finalout,
              const float* __restrict__ zerobuf, unsigned* __restrict__ flags) {
    extern __shared__ float sm[];
    float* Ws  = sm;                      // 512*18
    float* Asm = sm + 512 * 18;           // 2 * 32*66
    float* gsm = Asm + 2 * 32 * 66;       // 64*17

    const int tid = threadIdx.x, blk = blockIdx.x;

    // stage Whh slice: Ws[k*18 + g], g = q*4+j -> global row q*512 + blk*4 + j
    for (int e = tid; e < 16 * 512; e += 256) {
        int g = e >> 9, k = e & 511;
        int row = (g >> 2) * HH + blk * 4 + (g & 3);
        Ws[k * 18 + g] = Whh[(size_t)row * HH + k];
    }

    const int m2 = tid & 31, gq = tid >> 5;     // compute mapping: rows (2m2,2m2+1), gates (2gq,2gq+1)
    const int cm = tid >> 2, cj = tid & 3;      // cell mapping
    const int r0row = tid >> 3, r0kc = (tid & 7) * 4;  // staging: rows r0row / r0row+32, k chunk r0kc
    float creg = 0.f;
    __syncthreads();

    #pragma unroll 1
    for (int t = 0; t < TT; ++t) {
        const float* hp = t ? (seqout + (size_t)(t - 1) * BB * HH) : zerobuf;

        // prefetch this step's input-gate contribution (DRAM; hidden by GEMM below)
        size_t xb = ((size_t)t * BB + cm) * GG + blk * 4 + cj;
        float x0 = xg[xb], x1 = xg[xb + 512], x2 = xg[xb + 1024], x3 = xg[xb + 1536];

        // depth-2 register prefetch of h tiles (KC=32)
        float4 r[2][2];
        r[0][0] = *(const float4*)(hp + (size_t)r0row * HH + r0kc);
        r[0][1] = *(const float4*)(hp + (size_t)(r0row + 32) * HH + r0kc);
        r[1][0] = *(const float4*)(hp + (size_t)r0row * HH + 32 + r0kc);
        r[1][1] = *(const float4*)(hp + (size_t)(r0row + 32) * HH + 32 + r0kc);

        ull acc0 = 0ull, acc1 = 0ull;
        #pragma unroll 1
        for (int kt = 0; kt < 16; ++kt) {
            const int buf = kt & 1;
            float* Ab = Asm + buf * (32 * 66);
            #pragma unroll
            for (int u = 0; u < 4; ++u) {
                Ab[(r0kc + u) * 66 + r0row]      = ((const float*)&r[buf][0])[u];
                Ab[(r0kc + u) * 66 + r0row + 32] = ((const float*)&r[buf][1])[u];
            }
            if (kt + 2 < 16) {
                r[buf][0] = *(const float4*)(hp + (size_t)r0row * HH + (kt + 2) * 32 + r0kc);
                r[buf][1] = *(const float4*)(hp + (size_t)(r0row + 32) * HH + (kt + 2) * 32 + r0kc);
            }
            __syncthreads();
            const float* Wk = Ws + kt * 32 * 18;
            #pragma unroll
            for (int k = 0; k < 32; ++k) {
                ull a = *(const ull*)&Ab[k * 66 + 2 * m2];
                float2 b = *(const float2*)&Wk[k * 18 + 2 * gq];
                fma2(acc0, a, dup2(b.x));
                fma2(acc1, a, dup2(b.y));
            }
            // no trailing sync needed: 2 smem buffers + per-thread program order
        }

        // exchange gates through smem
        float2 p0 = unp(acc0), p1 = unp(acc1);
        gsm[(2 * m2) * 17 + 2 * gq]         = p0.x;
        gsm[(2 * m2 + 1) * 17 + 2 * gq]     = p0.y;
        gsm[(2 * m2) * 17 + 2 * gq + 1]     = p1.x;
        gsm[(2 * m2 + 1) * 17 + 2 * gq + 1] = p1.y;
        __syncthreads();

        float gi = sigf (gsm[cm * 17 +      cj] + x0);
        float gf = sigf (gsm[cm * 17 +  4 + cj] + x1);
        float gg = tanhf(gsm[cm * 17 +  8 + cj] + x2);
        float go = sigf (gsm[cm * 17 + 12 + cj] + x3);
        creg = gf * creg + gi * gg;
        float h = go * tanhf(creg);

        float* hout = (finalout && t == TT - 1) ? finalout
                                                : (seqout + (size_t)t * BB * HH);
        hout[cm * HH + blk * 4 + cj] = h;

        if (t < TT - 1) {
            __syncthreads();
            if (tid == 0) {
                __threadfence();
                *(volatile unsigned*)&flags[blk * 8] = (unsigned)(t + 1);
            }
            if (tid < NBLK) {
                while (*(volatile unsigned*)&flags[tid * 8] <= (unsigned)t) __nanosleep(32);
            }
            __syncthreads();
        }
    }
}

// ---------------- launch ----------------
extern "C" void kernel_launch(void* const* d_in, const int* in_sizes, int n_in,
                              void* d_out, int out_size) {
    const float* x    = (const float*)d_in[0];
    const float* Wih0 = (const float*)d_in[1];
    const float* Whh0 = (const float*)d_in[2];
    const float* bih0 = (const float*)d_in[3];
    const float* bhh0 = (const float*)d_in[4];
    const float* Wih1 = (const float*)d_in[5];
    const float* Whh1 = (const float*)d_in[6];
    const float* bih1 = (const float*)d_in[7];
    const float* bhh1 = (const float*)d_in[8];
    float* out = (float*)d_out;

    float *xTt, *xg0, *out0, *xg1, *out1, *zero;
    unsigned *f0, *f1;
    cudaGetSymbolAddress((void**)&xTt,  g_xTt);
    cudaGetSymbolAddress((void**)&xg0,  g_xg0);
    cudaGetSymbolAddress((void**)&out0, g_out0);
    cudaGetSymbolAddress((void**)&xg1,  g_xg1);
    cudaGetSymbolAddress((void**)&out1, g_out1);
    cudaGetSymbolAddress((void**)&zero, g_zero);
    cudaGetSymbolAddress((void**)&f0,   g_flag0);
    cudaGetSymbolAddress((void**)&f1,   g_flag1);

    const int smem = (512 * 18 + 2 * 32 * 66 + 64 * 17) * 4;
    cudaFuncSetAttribute(lstm_rec, cudaFuncAttributeMaxDynamicSharedMemorySize, smem);

    reset_kernel<<<1, 128>>>();

    dim3 tb(32, 8), tg(TT / 32, FF / 32, BB);
    transpose_x_kernel<<<tg, tb>>>(x);

    gemm_gates<FF><<<dim3(GG / 64, TT * BB / 64), 256>>>(xTt, Wih0, bih0, bhh0, xg0);
    lstm_rec<<<NBLK, 256, smem>>>(xg0, Whh0, out0, nullptr, zero, f0);
    gemm_gates<HH><<<dim3(GG / 64, TT * BB / 64), 256>>>(out0, Wih1, bih1, bhh1, xg1);
    lstm_rec<<<NBLK, 256, smem>>>(xg1, Whh1, out1, out, zero, f1);
}

// round 3
// speedup vs baseline: 1.0004x; 1.0004x over previous
#include <cuda_runtime.h>
#include <math.h>

#define BB 64
#define FF 128
#define TT 1024
#define HH 512
#define GG 2048   // 4*H
#define NBLK 128

typedef unsigned long long ull;

// ---------------- scratch (device globals; no allocation allowed) ----------------
__device__ float g_xTt [(size_t)TT * BB * FF];   // (T,B,F)   32 MB
__device__ float g_xg0 [(size_t)TT * BB * GG];   // (T*B,4H) 512 MB
__device__ float g_out0[(size_t)TT * BB * HH];   // (T,B,H)  128 MB
__device__ float g_xg1 [(size_t)TT * BB * GG];   // (T*B,4H) 512 MB
__device__ float g_out1[(size_t)TT * BB * HH];   // (T,B,H)  128 MB
__device__ float g_zero[BB * HH];                // stays zero forever
__device__ unsigned g_flag0[NBLK * 8];
__device__ unsigned g_flag1[NBLK * 8];

// ---------------- f32x2 packed-FMA helpers ----------------
__device__ __forceinline__ void fma2(ull& acc, ull a, ull b) {
    asm("fma.rn.f32x2 %0, %1, %2, %0;" : "+l"(acc) : "l"(a), "l"(b));
}
__device__ __forceinline__ ull dup2(float x) {
    ull r; asm("mov.b64 %0, {%1, %1};" : "=l"(r) : "f"(x)); return r;
}
__device__ __forceinline__ float2 unp(ull v) {
    float2 r; asm("mov.b64 {%0, %1}, %2;" : "=f"(r.x), "=f"(r.y) : "l"(v)); return r;
}
__device__ __forceinline__ float sigf(float x) { return 1.f / (1.f + __expf(-x)); }

// ---------------- reset barrier flags ----------------
__global__ void reset_kernel() {
    int i = threadIdx.x;
    if (i < NBLK) { g_flag0[i * 8] = 0u; g_flag1[i * 8] = 0u; }
}

// ---------------- transpose x (B,F,T) -> (T,B,F) ----------------
__global__ void transpose_x_kernel(const float* __restrict__ x) {
    __shared__ float tile[32][33];
    int b  = blockIdx.z;
    int t0 = blockIdx.x * 32;
    int f0 = blockIdx.y * 32;
    for (int i = threadIdx.y; i < 32; i += 8)
        tile[i][threadIdx.x] = x[(size_t)b * FF * TT + (size_t)(f0 + i) * TT + t0 + threadIdx.x];
    __syncthreads();
    for (int i = threadIdx.y; i < 32; i += 8)
        g_xTt[(size_t)(t0 + i) * BB * FF + (size_t)b * FF + f0 + threadIdx.x] = tile[threadIdx.x][i];
}

// ---------------- big GEMM: C(M,2048) = A(M,K) @ W(2048,K)^T + bih + bhh ----------------
// 64x64 block tile, KC=16, 256 threads, 4x4 per thread, f32x2 accumulation,
// double-buffered smem with register prefetch.
template <int K>
__global__ __launch_bounds__(256, 2)
void gemm_gates(const float* __restrict__ A, const float* __restrict__ W,
                const float* __restrict__ bih, const float* __restrict__ bhh,
                float* __restrict__ C) {
    __shared__ __align__(16) float As[2][16 * 68];
    __shared__ __align__(16) float Bs[2][16 * 68];
    const int tid = threadIdx.x, tx = tid & 15, ty = tid >> 4;
    const int n0 = blockIdx.x * 64, m0 = blockIdx.y * 64;
    const int srow = tid >> 2, skc = (tid & 3) * 4;

    const float* Ap = A + (size_t)(m0 + srow) * K + skc;
    const float* Wp = W + (size_t)(n0 + srow) * K + skc;
    float4 ra = *(const float4*)Ap;
    float4 rb = *(const float4*)Wp;

    ull acc[4][2];
    #pragma unroll
    for (int n = 0; n < 4; ++n) { acc[n][0] = 0ull; acc[n][1] = 0ull; }

    const int KT = K / 16;
    #pragma unroll 1
    for (int kt = 0; kt < KT; ++kt) {
        const int buf = kt & 1;
        float* Ab = &As[buf][0];
        float* Bb = &Bs[buf][0];
        Ab[(skc + 0) * 68 + srow] = ra.x; Ab[(skc + 1) * 68 + srow] = ra.y;
        Ab[(skc + 2) * 68 + srow] = ra.z; Ab[(skc + 3) * 68 + srow] = ra.w;
        Bb[(skc + 0) * 68 + srow] = rb.x; Bb[(skc + 1) * 68 + srow] = rb.y;
        Bb[(skc + 2) * 68 + srow] = rb.z; Bb[(skc + 3) * 68 + srow] = rb.w;
        if (kt + 1 < KT) {
            ra = *(const float4*)(Ap + (kt + 1) * 16);
            rb = *(const float4*)(Wp + (kt + 1) * 16);
        }
        __syncthreads();
        #pragma unroll
        for (int k = 0; k < 16; ++k) {
            ulonglong2 a = *(const ulonglong2*)&Ab[k * 68 + 4 * ty];
            float4 b = *(const float4*)&Bb[k * 68 + 4 * tx];
            ull b0 = dup2(b.x), b1 = dup2(b.y), b2 = dup2(b.z), b3 = dup2(b.w);
            fma2(acc[0][0], a.x, b0); fma2(acc[0][1], a.y, b0);
            fma2(acc[1][0], a.x, b1); fma2(acc[1][1], a.y, b1);
            fma2(acc[2][0], a.x, b2); fma2(acc[2][1], a.y, b2);
            fma2(acc[3][0], a.x, b3); fma2(acc[3][1], a.y, b3);
        }
        __syncthreads();
    }

    float bv[4];
    #pragma unroll
    for (int u = 0; u < 4; ++u)
        bv[u] = bih[n0 + 4 * tx + u] + bhh[n0 + 4 * tx + u];

    #pragma unroll
    for (int h = 0; h < 2; ++h) {
        float2 p0 = unp(acc[0][h]), p1 = unp(acc[1][h]);
        float2 p2 = unp(acc[2][h]), p3 = unp(acc[3][h]);
        size_t r0 = (size_t)(m0 + 4 * ty + 2 * h) * GG + n0 + 4 * tx;
        *(float4*)&C[r0]      = make_float4(p0.x + bv[0], p1.x + bv[1], p2.x + bv[2], p3.x + bv[3]);
        *(float4*)&C[r0 + GG] = make_float4(p0.y + bv[0], p1.y + bv[1], p2.y + bv[2], p3.y + bv[3]);
    }
}

// ---------------- persistent LSTM recurrence ----------------
// 128 blocks (co-resident), block blk owns h-cols [4*blk, 4*blk+4).
// Whh slice (16 rows x 512) cached in SMEM for all steps. Per step:
// gates(64x16) = h(64,512) @ Whh_slice^T (f32x2), + precomputed xg[t], cell, h-write, grid barrier.
__global__ __launch_bounds__(256)
void lstm_rec(const float* __restrict__ xg, const float* __restrict__ Whh,
              float* __restrict__ seqout, float* __restrict__ finalout,
              const float* __restrict__ zerobuf, unsigned* __restrict__ flags) {
    extern __shared__ float sm[];
    float* Ws  = sm;                      // 512*18
    float* Asm = sm + 512 * 18;           // 2 * 32*66
    float* gsm = Asm + 2 * 32 * 66;       // 64*17

    const int tid = threadIdx.x, blk = blockIdx.x;

    // stage Whh slice: Ws[k*18 + g], g = q*4+j -> global row q*512 + blk*4 + j
    for (int e = tid; e < 16 * 512; e += 256) {
        int g = e >> 9, k = e & 511;
        int row = (g >> 2) * HH + blk * 4 + (g & 3);
        Ws[k * 18 + g] = Whh[(size_t)row * HH + k];
    }

    const int m2 = tid & 31, gq = tid >> 5;     // compute mapping: rows (2m2,2m2+1), gates (2gq,2gq+1)
    const int cm = tid >> 2, cj = tid & 3;      // cell mapping
    const int r0row = tid >> 3, r0kc = (tid & 7) * 4;  // staging: rows r0row / r0row+32, k chunk r0kc
    float creg = 0.f;
    __syncthreads();

    #pragma unroll 1
    for (int t = 0; t < TT; ++t) {
        const float* hp = t ? (seqout + (size_t)(t - 1) * BB * HH) : zerobuf;

        // prefetch this step's input-gate contribution (DRAM; hidden by GEMM below)
        size_t xb = ((size_t)t * BB + cm) * GG + blk * 4 + cj;
        float x0 = xg[xb], x1 = xg[xb + 512], x2 = xg[xb + 1024], x3 = xg[xb + 1536];

        // depth-2 register prefetch of h tiles (KC=32)
        float4 r[2][2];
        r[0][0] = *(const float4*)(hp + (size_t)r0row * HH + r0kc);
        r[0][1] = *(const float4*)(hp + (size_t)(r0row + 32) * HH + r0kc);
        r[1][0] = *(const float4*)(hp + (size_t)r0row * HH + 32 + r0kc);
        r[1][1] = *(const float4*)(hp + (size_t)(r0row + 32) * HH + 32 + r0kc);

        ull acc0 = 0ull, acc1 = 0ull;
        #pragma unroll 1
        for (int kt = 0; kt < 16; ++kt) {
            const int buf = kt & 1;
            float* Ab = Asm + buf * (32 * 66);
            #pragma unroll
            for (int u = 0; u < 4; ++u) {
                Ab[(r0kc + u) * 66 + r0row]      = ((const float*)&r[buf][0])[u];
                Ab[(r0kc + u) * 66 + r0row + 32] = ((const float*)&r[buf][1])[u];
            }
            if (kt + 2 < 16) {
                r[buf][0] = *(const float4*)(hp + (size_t)r0row * HH + (kt + 2) * 32 + r0kc);
                r[buf][1] = *(const float4*)(hp + (size_t)(r0row + 32) * HH + (kt + 2) * 32 + r0kc);
            }
            __syncthreads();
            const float* Wk = Ws + kt * 32 * 18;
            #pragma unroll
            for (int k = 0; k < 32; ++k) {
                ull a = *(const ull*)&Ab[k * 66 + 2 * m2];
                float2 b = *(const float2*)&Wk[k * 18 + 2 * gq];
                fma2(acc0, a, dup2(b.x));
                fma2(acc1, a, dup2(b.y));
            }
            // no trailing sync needed: 2 smem buffers + per-thread program order
        }

        // exchange gates through smem
        float2 p0 = unp(acc0), p1 = unp(acc1);
        gsm[(2 * m2) * 17 + 2 * gq]         = p0.x;
        gsm[(2 * m2 + 1) * 17 + 2 * gq]     = p0.y;
        gsm[(2 * m2) * 17 + 2 * gq + 1]     = p1.x;
        gsm[(2 * m2 + 1) * 17 + 2 * gq + 1] = p1.y;
        __syncthreads();

        float gi = sigf (gsm[cm * 17 +      cj] + x0);
        float gf = sigf (gsm[cm * 17 +  4 + cj] + x1);
        float gg = tanhf(gsm[cm * 17 +  8 + cj] + x2);
        float go = sigf (gsm[cm * 17 + 12 + cj] + x3);
        creg = gf * creg + gi * gg;
        float h = go * tanhf(creg);

        float* hout = (finalout && t == TT - 1) ? finalout
                                                : (seqout + (size_t)t * BB * HH);
        hout[cm * HH + blk * 4 + cj] = h;

        if (t < TT - 1) {
            __syncthreads();
            if (tid == 0) {
                __threadfence();
                *(volatile unsigned*)&flags[blk * 8] = (unsigned)(t + 1);
            }
            if (tid < NBLK) {
                while (*(volatile unsigned*)&flags[tid * 8] <= (unsigned)t) __nanosleep(32);
            }
            __syncthreads();
        }
    }
}

// ---------------- launch ----------------
extern "C" void kernel_launch(void* const* d_in, const int* in_sizes, int n_in,
                              void* d_out, int out_size) {
    const float* x    = (const float*)d_in[0];
    const float* Wih0 = (const float*)d_in[1];
    const float* Whh0 = (const float*)d_in[2];
    const float* bih0 = (const float*)d_in[3];
    const float* bhh0 = (const float*)d_in[4];
    const float* Wih1 = (const float*)d_in[5];
    const float* Whh1 = (const float*)d_in[6];
    const float* bih1 = (const float*)d_in[7];
    const float* bhh1 = (const float*)d_in[8];
    float* out = (float*)d_out;

    float *xTt, *xg0, *out0, *xg1, *out1, *zero;
    unsigned *f0, *f1;
    cudaGetSymbolAddress((void**)&xTt,  g_xTt);
    cudaGetSymbolAddress((void**)&xg0,  g_xg0);
    cudaGetSymbolAddress((void**)&out0, g_out0);
    cudaGetSymbolAddress((void**)&xg1,  g_xg1);
    cudaGetSymbolAddress((void**)&out1, g_out1);
    cudaGetSymbolAddress((void**)&zero, g_zero);
    cudaGetSymbolAddress((void**)&f0,   g_flag0);
    cudaGetSymbolAddress((void**)&f1,   g_flag1);

    const int smem = (512 * 18 + 2 * 32 * 66 + 64 * 17) * 4;
    cudaFuncSetAttribute(lstm_rec, cudaFuncAttributeMaxDynamicSharedMemorySize, smem);

    reset_kernel<<<1, 128>>>();

    dim3 tb(32, 8), tg(TT / 32, FF / 32, BB);
    transpose_x_kernel<<<tg, tb>>>(x);

    gemm_gates<FF><<<dim3(GG / 64, TT * BB / 64), 256>>>(xTt, Wih0, bih0, bhh0, xg0);
    lstm_rec<<<NBLK, 256, smem>>>(xg0, Whh0, out0, nullptr, zero, f0);
    gemm_gates<HH><<<dim3(GG / 64, TT * BB / 64), 256>>>(out0, Wih1, bih1, bhh1, xg1);
    lstm_rec<<<NBLK, 256, smem>>>(xg1, Whh1, out1, out, zero, f1);
}

// round 4
// speedup vs baseline: 1.6352x; 1.6345x over previous
#include <cuda_runtime.h>
#include <cuda_fp16.h>
#include <math.h>

#define BB 64
#define FF 128
#define TT 1024
#define HH 512
#define GG 2048
#define NBLK 128

typedef unsigned long long ull;

// ---------------- device globals (no allocation allowed) ----------------
__device__ float   g_xTt[(size_t)TT * BB * FF];   // (T*B, F)  32 MB
__device__ float   g_xg [(size_t)TT * BB * GG];   // (T*B, 4H) 512 MB (reused by both layers)
__device__ float   g_seq[(size_t)TT * BB * HH];   // h fp32 (T*B, H) 128 MB
__device__ __half  g_h16[(size_t)TT * BB * HH];   // h fp16            64 MB
__device__ __half  g_z16[BB * HH];                // zeros (never written)
__device__ unsigned g_flag[2][NBLK * 8];

// ---------------- helpers ----------------
__device__ __forceinline__ void fma2(ull& acc, ull a, ull b) {
    asm("fma.rn.f32x2 %0, %1, %2, %0;" : "+l"(acc) : "l"(a), "l"(b));
}
__device__ __forceinline__ ull add2(ull a, ull b) {
    ull r; asm("add.rn.f32x2 %0, %1, %2;" : "=l"(r) : "l"(a), "l"(b)); return r;
}
__device__ __forceinline__ ull pk(float a, float b) {
    ull r; asm("mov.b64 %0, {%1, %2};" : "=l"(r) : "f"(a), "f"(b)); return r;
}
__device__ __forceinline__ ull dup2(float x) {
    ull r; asm("mov.b64 %0, {%1, %1};" : "=l"(r) : "f"(x)); return r;
}
__device__ __forceinline__ float2 unp(ull v) {
    float2 r; asm("mov.b64 {%0, %1}, %2;" : "=f"(r.x), "=f"(r.y) : "l"(v)); return r;
}
__device__ __forceinline__ float sigf(float x) { return 1.f / (1.f + __expf(-x)); }

// ---------------- reset flags ----------------
__global__ void reset_kernel() {
    int i = threadIdx.x;
    for (int e = i; e < NBLK * 8; e += 256) { g_flag[0][e] = 0u; g_flag[1][e] = 0u; }
}

// ---------------- transpose x (B,F,T) -> (T*B, F) ----------------
__global__ void transpose_x_kernel(const float* __restrict__ x) {
    __shared__ float tile[32][33];
    int b  = blockIdx.z;
    int t0 = blockIdx.x * 32;
    int f0 = blockIdx.y * 32;
    for (int i = threadIdx.y; i < 32; i += 8)
        tile[i][threadIdx.x] = x[(size_t)b * FF * TT + (size_t)(f0 + i) * TT + t0 + threadIdx.x];
    __syncthreads();
    for (int i = threadIdx.y; i < 32; i += 8)
        g_xTt[((size_t)(t0 + i) * BB + b) * FF + f0 + threadIdx.x] = tile[threadIdx.x][i];
}

// ---------------- big GEMM: C(M,2048) = A(M,K) @ W(2048,K)^T + bih + bhh ----------------
// 128x128 tile, KC=16, 256 threads, 8x8 microtile, f32x2 accumulation.
template <int K>
__global__ __launch_bounds__(256, 2)
void gemm_gates(const float* __restrict__ A, const float* __restrict__ W,
                const float* __restrict__ bih, const float* __restrict__ bhh,
                float* __restrict__ C) {
    __shared__ __align__(16) float As[2][16][132];
    __shared__ __align__(16) float Bs[2][16][132];
    const int tid = threadIdx.x;
    const int m0 = blockIdx.y * 128, n0 = blockIdx.x * 128;
    const int srow = tid >> 1;            // 0..127
    const int sk0  = (tid & 1) * 8;       // 0 or 8

    const float* Ap = A + (size_t)(m0 + srow) * K + sk0;
    const float* Wp = W + (size_t)(n0 + srow) * K + sk0;
    float4 ra0 = *(const float4*)(Ap);
    float4 ra1 = *(const float4*)(Ap + 4);
    float4 rb0 = *(const float4*)(Wp);
    float4 rb1 = *(const float4*)(Wp + 4);

    const int mi = (tid >> 4) * 8;
    const int ni = (tid & 15) * 8;

    ull acc[8][4];
    #pragma unroll
    for (int n = 0; n < 8; ++n)
        #pragma unroll
        for (int p = 0; p < 4; ++p) acc[n][p] = 0ull;

    const int KT = K / 16;
    #pragma unroll 1
    for (int kt = 0; kt < KT; ++kt) {
        const int buf = kt & 1;
        #pragma unroll
        for (int c = 0; c < 4; ++c) {
            As[buf][sk0 + c][srow]     = ((const float*)&ra0)[c];
            As[buf][sk0 + 4 + c][srow] = ((const float*)&ra1)[c];
            Bs[buf][sk0 + c][srow]     = ((const float*)&rb0)[c];
            Bs[buf][sk0 + 4 + c][srow] = ((const float*)&rb1)[c];
        }
        if (kt + 1 < KT) {
            ra0 = *(const float4*)(Ap + (kt + 1) * 16);
            ra1 = *(const float4*)(Ap + (kt + 1) * 16 + 4);
            rb0 = *(const float4*)(Wp + (kt + 1) * 16);
            rb1 = *(const float4*)(Wp + (kt + 1) * 16 + 4);
        }
        __syncthreads();
        #pragma unroll
        for (int k = 0; k < 16; ++k) {
            ulonglong2 a0 = *(const ulonglong2*)&As[buf][k][mi];
            ulonglong2 a1 = *(const ulonglong2*)&As[buf][k][mi + 4];
            float4 b0 = *(const float4*)&Bs[buf][k][ni];
            float4 b1 = *(const float4*)&Bs[buf][k][ni + 4];
            ull am[4] = {a0.x, a0.y, a1.x, a1.y};
            float bs[8] = {b0.x, b0.y, b0.z, b0.w, b1.x, b1.y, b1.z, b1.w};
            #pragma unroll
            for (int n = 0; n < 8; ++n) {
                ull bb = dup2(bs[n]);
                fma2(acc[n][0], am[0], bb);
                fma2(acc[n][1], am[1], bb);
                fma2(acc[n][2], am[2], bb);
                fma2(acc[n][3], am[3], bb);
            }
        }
        __syncthreads();
    }

    float bn[8];
    #pragma unroll
    for (int u = 0; u < 8; ++u) bn[u] = bih[n0 + ni + u] + bhh[n0 + ni + u];

    #pragma unroll
    for (int p = 0; p < 4; ++p) {
        float2 v[8];
        #pragma unroll
        for (int n = 0; n < 8; ++n) v[n] = unp(acc[n][p]);
        size_t r0 = (size_t)(m0 + mi + 2 * p) * GG + n0 + ni;
        *(float4*)&C[r0]          = make_float4(v[0].x + bn[0], v[1].x + bn[1], v[2].x + bn[2], v[3].x + bn[3]);
        *(float4*)&C[r0 + 4]      = make_float4(v[4].x + bn[4], v[5].x + bn[5], v[6].x + bn[6], v[7].x + bn[7]);
        *(float4*)&C[r0 + GG]     = make_float4(v[0].y + bn[0], v[1].y + bn[1], v[2].y + bn[2], v[3].y + bn[3]);
        *(float4*)&C[r0 + GG + 4] = make_float4(v[4].y + bn[4], v[5].y + bn[5], v[6].y + bn[6], v[7].y + bn[7]);
    }
}

// ---------------- persistent LSTM recurrence ----------------
// 128 blocks, 256 threads. Warp w owns k-slice [64w,64w+64); lane = (g 0..15, ms 0..1).
// Whh held in registers (32 f32x2/thread) for all steps. h staged fp16->fp32 SMEM,
// row-group pipelined. Partials reduced via SMEM, fused cell, flag grid-barrier.
__global__ __launch_bounds__(256, 1)
void lstm_rec(const float* __restrict__ xg, const __half* __restrict__ z16,
              const float* __restrict__ Whh,
              float* __restrict__ seq, __half* __restrict__ h16,
              float* __restrict__ finalout, unsigned* __restrict__ flags) {
    extern __shared__ float sm[];
    float* Hs   = sm;                 // [64][516] fp32
    float* part = sm + 64 * 516;      // [8][64][17]

    const int tid = threadIdx.x, blk = blockIdx.x;
    const int w = tid >> 5, lane = tid & 31;
    const int g = lane & 15, ms = lane >> 4;
    const int q = g >> 2, j = g & 3;
    const int cm = tid >> 2, cj = tid & 3;          // cell: batch row, h-col
    const int col = blk * 4 + cj;

    // weights -> registers (once)
    ull w2[32];
    {
        const int r = q * HH + blk * 4 + j;
        const float4* wp = (const float4*)(Whh + (size_t)r * HH + w * 64);
        #pragma unroll
        for (int u = 0; u < 16; ++u) {
            float4 f = wp[u];
            w2[2 * u]     = pk(f.x, f.y);
            w2[2 * u + 1] = pk(f.z, f.w);
        }
    }

    float creg = 0.f;

    #pragma unroll 1
    for (int t = 0; t < TT; ++t) {
        const __half* hp = t ? (h16 + (size_t)(t - 1) * BB * HH) : z16;

        // prefetch this step's precomputed input-gate terms
        size_t xb = ((size_t)t * BB + cm) * GG + col;
        float x0 = xg[xb], x1 = xg[xb + 512], x2 = xg[xb + 1024], x3 = xg[xb + 1536];

        // ---- staging (per-warp, pipelined by row-group) ----
        // group gi covers rows {gi*8..gi*8+7} and {32+gi*8..32+gi*8+7}; lane stages 4 chunks.
        uint4 st[4];
        int srl[4], sc8[4];
        #pragma unroll
        for (int u = 0; u < 4; ++u) {
            int ch = lane * 4 + u;
            srl[u] = ch >> 3;  sc8[u] = ch & 7;
        }
        #pragma unroll
        for (int u = 0; u < 4; ++u) {
            int row = (srl[u] < 8) ? srl[u] : (24 + srl[u]);   // gi=0
            st[u] = *(const uint4*)(hp + (size_t)row * HH + w * 64 + sc8[u] * 8);
        }
        #pragma unroll
        for (int u = 0; u < 4; ++u) {
            int row = (srl[u] < 8) ? srl[u] : (24 + srl[u]);
            const __half2* h2 = (const __half2*)&st[u];
            float* dst = Hs + row * 516 + w * 64 + sc8[u] * 8;
            float2 f0 = __half22float2(h2[0]), f1 = __half22float2(h2[1]);
            float2 f2 = __half22float2(h2[2]), f3 = __half22float2(h2[3]);
            *(float4*)(dst)     = make_float4(f0.x, f0.y, f1.x, f1.y);
            *(float4*)(dst + 4) = make_float4(f2.x, f2.y, f3.x, f3.y);
        }
        __syncwarp();

        #pragma unroll 1
        for (int gi = 0; gi < 4; ++gi) {
            if (gi < 3) {
                #pragma unroll
                for (int u = 0; u < 4; ++u) {
                    int row = (gi + 1) * 8 + ((srl[u] < 8) ? srl[u] : (24 + srl[u]));
                    st[u] = *(const uint4*)(hp + (size_t)row * HH + w * 64 + sc8[u] * 8);
                }
            }
            // compute 8 m-rows of this group (own ms half)
            #pragma unroll 1
            for (int mi8 = 0; mi8 < 8; ++mi8) {
                int m = ms * 32 + gi * 8 + mi8;
                const ulonglong2* hrow = (const ulonglong2*)(Hs + m * 516 + w * 64);
                ull a0 = 0ull, a1 = 0ull, a2 = 0ull, a3 = 0ull;
                #pragma unroll
                for (int i = 0; i < 16; i += 2) {
                    ulonglong2 hA = hrow[i];
                    ulonglong2 hB = hrow[i + 1];
                    fma2(a0, hA.x, w2[2 * i]);
                    fma2(a1, hA.y, w2[2 * i + 1]);
                    fma2(a2, hB.x, w2[2 * i + 2]);
                    fma2(a3, hB.y, w2[2 * i + 3]);
                }
                float2 s = unp(add2(add2(a0, a2), add2(a1, a3)));
                part[w * 1088 + m * 17 + g] = s.x + s.y;
            }
            if (gi < 3) {
                #pragma unroll
                for (int u = 0; u < 4; ++u) {
                    int row = (gi + 1) * 8 + ((srl[u] < 8) ? srl[u] : (24 + srl[u]));
                    const __half2* h2 = (const __half2*)&st[u];
                    float* dst = Hs + row * 516 + w * 64 + sc8[u] * 8;
                    float2 f0 = __half22float2(h2[0]), f1 = __half22float2(h2[1]);
                    float2 f2 = __half22float2(h2[2]), f3 = __half22float2(h2[3]);
                    *(float4*)(dst)     = make_float4(f0.x, f0.y, f1.x, f1.y);
                    *(float4*)(dst + 4) = make_float4(f2.x, f2.y, f3.x, f3.y);
                }
                __syncwarp();
            }
        }
        __syncthreads();

        // ---- reduce partials + cell ----
        float gate[4];
        #pragma unroll
        for (int qq = 0; qq < 4; ++qq) {
            float s = 0.f;
            #pragma unroll
            for (int ww = 0; ww < 8; ++ww)
                s += part[ww * 1088 + cm * 17 + qq * 4 + cj];
            gate[qq] = s;
        }
        float gi_ = sigf (gate[0] + x0);
        float gf_ = sigf (gate[1] + x1);
        float gz_ = tanhf(gate[2] + x2);
        float go_ = sigf (gate[3] + x3);
        creg = gf_ * creg + gi_ * gz_;
        float h = go_ * tanhf(creg);

        size_t ho = ((size_t)t * BB + cm) * HH + col;
        seq[ho] = h;
        h16[ho] = __float2half(h);
        if (finalout && t == TT - 1) finalout[cm * HH + col] = h;

        // ---- grid barrier ----
        if (t < TT - 1) {
            __threadfence();
            __syncthreads();
            if (tid == 0) *(volatile unsigned*)&flags[blk * 8] = (unsigned)(t + 1);
            if (tid < NBLK) {
                while (*(volatile unsigned*)&flags[tid * 8] < (unsigned)(t + 1)) __nanosleep(40);
            }
            __threadfence();
            __syncthreads();
        }
    }
}

// ---------------- launch ----------------
extern "C" void kernel_launch(void* const* d_in, const int* in_sizes, int n_in,
                              void* d_out, int out_size) {
    const float* x    = (const float*)d_in[0];
    const float* Wih0 = (const float*)d_in[1];
    const float* Whh0 = (const float*)d_in[2];
    const float* bih0 = (const float*)d_in[3];
    const float* bhh0 = (const float*)d_in[4];
    const float* Wih1 = (const float*)d_in[5];
    const float* Whh1 = (const float*)d_in[6];
    const float* bih1 = (const float*)d_in[7];
    const float* bhh1 = (const float*)d_in[8];
    float* out = (float*)d_out;

    float *xTt, *xg, *seq;
    __half *h16, *z16;
    unsigned* flags;
    cudaGetSymbolAddress((void**)&xTt,  g_xTt);
    cudaGetSymbolAddress((void**)&xg,   g_xg);
    cudaGetSymbolAddress((void**)&seq,  g_seq);
    cudaGetSymbolAddress((void**)&h16,  g_h16);
    cudaGetSymbolAddress((void**)&z16,  g_z16);
    cudaGetSymbolAddress((void**)&flags, g_flag);

    const int smem = (64 * 516 + 8 * 64 * 17) * 4;
    cudaFuncSetAttribute(lstm_rec, cudaFuncAttributeMaxDynamicSharedMemorySize, smem);

    reset_kernel<<<1, 256>>>();

    dim3 tb(32, 8), tg(TT / 32, FF / 32, BB);
    transpose_x_kernel<<<tg, tb>>>(x);

    gemm_gates<FF><<<dim3(GG / 128, TT * BB / 128), 256>>>(xTt, Wih0, bih0, bhh0, xg);
    lstm_rec<<<NBLK, 256, smem>>>(xg, z16, Whh0, seq, h16, nullptr, flags);
    gemm_gates<HH><<<dim3(GG / 128, TT * BB / 128), 256>>>(seq, Wih1, bih1, bhh1, xg);
    lstm_rec<<<NBLK, 256, smem>>>(xg, z16, Whh1, seq, h16, out, flags + NBLK * 8);
}

// round 5
// speedup vs baseline: 1.9757x; 1.2082x over previous
#include <cuda_runtime.h>
#include <cuda_fp16.h>
#include <math.h>

#define BB 64
#define FF 128
#define TT 1024
#define HH 512
#define GG 2048
#define NBLK 128

typedef unsigned long long ull;

// ---------------- device globals (no allocation allowed) ----------------
__device__ float   g_xTt[(size_t)TT * BB * FF];   // (T*B, F)
__device__ float   g_xg [(size_t)TT * BB * GG];   // (T*B, 4H) reused both layers
__device__ float   g_seq[(size_t)TT * BB * HH];   // layer0 h fp32 (T*B, H) for GEMM2
__device__ __half  g_h16[(size_t)TT * HH * BB];   // h fp16 [t][k][m]
__device__ __half  g_z16[HH * BB];                // zeros (never written)
__device__ unsigned g_flag[2][NBLK * 8];

// ---------------- helpers ----------------
__device__ __forceinline__ void fma2(ull& acc, ull a, ull b) {
    asm("fma.rn.f32x2 %0, %1, %2, %0;" : "+l"(acc) : "l"(a), "l"(b));
}
__device__ __forceinline__ ull dup2(float x) {
    ull r; asm("mov.b64 %0, {%1, %1};" : "=l"(r) : "f"(x)); return r;
}
__device__ __forceinline__ float2 unp(ull v) {
    float2 r; asm("mov.b64 {%0, %1}, %2;" : "=f"(r.x), "=f"(r.y) : "l"(v)); return r;
}
__device__ __forceinline__ float sigf(float x) { return 1.f / (1.f + __expf(-x)); }

__device__ __forceinline__ void st_release(unsigned* p, unsigned v) {
    asm volatile("st.release.gpu.global.u32 [%0], %1;" :: "l"(p), "r"(v) : "memory");
}
__device__ __forceinline__ unsigned ld_acquire(const unsigned* p) {
    unsigned v;
    asm volatile("ld.acquire.gpu.global.u32 %0, [%1];" : "=r"(v) : "l"(p) : "memory");
    return v;
}

// ---------------- reset flags ----------------
__global__ void reset_kernel() {
    for (int e = threadIdx.x; e < NBLK * 8; e += 256) { g_flag[0][e] = 0u; g_flag[1][e] = 0u; }
}

// ---------------- transpose x (B,F,T) -> (T*B, F) ----------------
__global__ void transpose_x_kernel(const float* __restrict__ x) {
    __shared__ float tile[32][33];
    int b  = blockIdx.z;
    int t0 = blockIdx.x * 32;
    int f0 = blockIdx.y * 32;
    for (int i = threadIdx.y; i < 32; i += 8)
        tile[i][threadIdx.x] = x[(size_t)b * FF * TT + (size_t)(f0 + i) * TT + t0 + threadIdx.x];
    __syncthreads();
    for (int i = threadIdx.y; i < 32; i += 8)
        g_xTt[((size_t)(t0 + i) * BB + b) * FF + f0 + threadIdx.x] = tile[threadIdx.x][i];
}

// ---------------- big GEMM: C(M,2048) = A(M,K) @ W(2048,K)^T + bih + bhh ----------------
template <int K>
__global__ __launch_bounds__(256, 2)
void gemm_gates(const float* __restrict__ A, const float* __restrict__ W,
                const float* __restrict__ bih, const float* __restrict__ bhh,
                float* __restrict__ C) {
    __shared__ __align__(16) float As[2][16][132];
    __shared__ __align__(16) float Bs[2][16][132];
    const int tid = threadIdx.x;
    const int m0 = blockIdx.y * 128, n0 = blockIdx.x * 128;
    const int srow = tid >> 1;
    const int sk0  = (tid & 1) * 8;

    const float* Ap = A + (size_t)(m0 + srow) * K + sk0;
    const float* Wp = W + (size_t)(n0 + srow) * K + sk0;
    float4 ra0 = *(const float4*)(Ap);
    float4 ra1 = *(const float4*)(Ap + 4);
    float4 rb0 = *(const float4*)(Wp);
    float4 rb1 = *(const float4*)(Wp + 4);

    const int mi = (tid >> 4) * 8;
    const int ni = (tid & 15) * 8;

    ull acc[8][4];
    #pragma unroll
    for (int n = 0; n < 8; ++n)
        #pragma unroll
        for (int p = 0; p < 4; ++p) acc[n][p] = 0ull;

    const int KT = K / 16;
    #pragma unroll 1
    for (int kt = 0; kt < KT; ++kt) {
        const int buf = kt & 1;
        #pragma unroll
        for (int c = 0; c < 4; ++c) {
            As[buf][sk0 + c][srow]     = ((const float*)&ra0)[c];
            As[buf][sk0 + 4 + c][srow] = ((const float*)&ra1)[c];
            Bs[buf][sk0 + c][srow]     = ((const float*)&rb0)[c];
            Bs[buf][sk0 + 4 + c][srow] = ((const float*)&rb1)[c];
        }
        if (kt + 1 < KT) {
            ra0 = *(const float4*)(Ap + (kt + 1) * 16);
            ra1 = *(const float4*)(Ap + (kt + 1) * 16 + 4);
            rb0 = *(const float4*)(Wp + (kt + 1) * 16);
            rb1 = *(const float4*)(Wp + (kt + 1) * 16 + 4);
        }
        __syncthreads();
        #pragma unroll
        for (int k = 0; k < 16; ++k) {
            ulonglong2 a0 = *(const ulonglong2*)&As[buf][k][mi];
            ulonglong2 a1 = *(const ulonglong2*)&As[buf][k][mi + 4];
            float4 b0 = *(const float4*)&Bs[buf][k][ni];
            float4 b1 = *(const float4*)&Bs[buf][k][ni + 4];
            ull am[4] = {a0.x, a0.y, a1.x, a1.y};
            float bs[8] = {b0.x, b0.y, b0.z, b0.w, b1.x, b1.y, b1.z, b1.w};
            #pragma unroll
            for (int n = 0; n < 8; ++n) {
                ull bb = dup2(bs[n]);
                fma2(acc[n][0], am[0], bb);
                fma2(acc[n][1], am[1], bb);
                fma2(acc[n][2], am[2], bb);
                fma2(acc[n][3], am[3], bb);
            }
        }
        __syncthreads();
    }

    float bn[8];
    #pragma unroll
    for (int u = 0; u < 8; ++u) bn[u] = bih[n0 + ni + u] + bhh[n0 + ni + u];

    #pragma unroll
    for (int p = 0; p < 4; ++p) {
        float2 v[8];
        #pragma unroll
        for (int n = 0; n < 8; ++n) v[n] = unp(acc[n][p]);
        size_t r0 = (size_t)(m0 + mi + 2 * p) * GG + n0 + ni;
        *(float4*)&C[r0]          = make_float4(v[0].x + bn[0], v[1].x + bn[1], v[2].x + bn[2], v[3].x + bn[3]);
        *(float4*)&C[r0 + 4]      = make_float4(v[4].x + bn[4], v[5].x + bn[5], v[6].x + bn[6], v[7].x + bn[7]);
        *(float4*)&C[r0 + GG]     = make_float4(v[0].y + bn[0], v[1].y + bn[1], v[2].y + bn[2], v[3].y + bn[3]);
        *(float4*)&C[r0 + GG + 4] = make_float4(v[4].y + bn[4], v[5].y + bn[5], v[6].y + bn[6], v[7].y + bn[7]);
    }
}

// ---------------- persistent LSTM recurrence ----------------
// 128 blocks, 256 threads, 1 block/SM. Block owns h-cols [4*blk, 4*blk+4).
// Warp w owns k-slice [64w, 64w+64): stages its own slice h16->Hs (k-major),
// software-pipelined (4 chunks of 16 k), then computes 16 gate-cols x 64 m over
// its slice. Per k: 3 LDS.128 -> 16 fma2. Cross-warp reduce via SMEM, fused cell,
// release/acquire flag grid-barrier (no L1 flush).
__global__ __launch_bounds__(256, 1)
void lstm_rec(const float* __restrict__ xg, const __half* __restrict__ z16,
              const float* __restrict__ Whh,
              float* __restrict__ seq, __half* __restrict__ h16,
              float* __restrict__ finalout, unsigned* __restrict__ flags) {
    extern __shared__ float sm[];
    float* Hs   = sm;                     // [512][68] k-major h (fp32)
    float* Ws   = sm + 512 * 68;          // [512][16]: k*16 + j*4 + q
    float* part = Ws + 512 * 16;          // [8][64*17]

    const int tid = threadIdx.x, blk = blockIdx.x;
    const int w = tid >> 5, lane = tid & 31;
    const int j = lane & 3, mg = lane >> 2;
    const int ks = w * 64;

    // stage Whh slice: Ws[k*16 + jj*4 + qq] = Whh[(qq*512 + blk*4 + jj)*512 + k]
    for (int e = tid; e < 16 * 512; e += 256) {
        int g = e >> 9, k = e & 511;
        int jj = g >> 2, qq = g & 3;
        Ws[k * 16 + jj * 4 + qq] = Whh[(size_t)(qq * HH + blk * 4 + jj) * HH + k];
    }

    const int cm = tid & 63, cjj = tid >> 6;
    const int col = blk * 4 + cjj;
    // staging lane mapping: row r = lane>>1 within chunk, half hf = lane&1 (m-range hf*32..+32)
    const int r = lane >> 1, hf = lane & 1;
    float creg = 0.f;
    __syncthreads();

    #pragma unroll 1
    for (int t = 0; t < TT; ++t) {
        const __half* hp = t ? (h16 + (size_t)(t - 1) * HH * BB) : z16;

        // this step's precomputed input-gate terms (in flight under staging/compute)
        size_t xb = ((size_t)t * BB + cm) * GG + col;
        float x0 = xg[xb], x1 = xg[xb + 512], x2 = xg[xb + 1024], x3 = xg[xb + 1536];

        ull acc[4][4];
        #pragma unroll
        for (int p = 0; p < 4; ++p)
            #pragma unroll
            for (int q = 0; q < 4; ++q) acc[p][q] = 0ull;

        // prefetch chunk 0 (own k-slice rows ks..ks+16)
        uint4 stg[4];
        {
            const uint4* src = (const uint4*)(hp + (size_t)(ks + r) * BB + hf * 32);
            stg[0] = src[0]; stg[1] = src[1]; stg[2] = src[2]; stg[3] = src[3];
        }

        #pragma unroll 1
        for (int c = 0; c < 4; ++c) {
            // store chunk c to Hs (k-major, pitch 68)
            {
                int kk = ks + c * 16 + r;
                float* dst = Hs + kk * 68 + hf * 32;
                #pragma unroll
                for (int u = 0; u < 4; ++u) {
                    const __half2* h2 = (const __half2*)&stg[u];
                    float2 f0 = __half22float2(h2[0]), f1 = __half22float2(h2[1]);
                    float2 f2 = __half22float2(h2[2]), f3 = __half22float2(h2[3]);
                    *(float4*)(dst + u * 8)     = make_float4(f0.x, f0.y, f1.x, f1.y);
                    *(float4*)(dst + u * 8 + 4) = make_float4(f2.x, f2.y, f3.x, f3.y);
                }
            }
            __syncwarp();
            // prefetch chunk c+1 (overlaps with compute below)
            if (c < 3) {
                const uint4* src = (const uint4*)(hp + (size_t)(ks + (c + 1) * 16 + r) * BB + hf * 32);
                stg[0] = src[0]; stg[1] = src[1]; stg[2] = src[2]; stg[3] = src[3];
            }
            // compute chunk c: 16 k, per k: 3 LDS.128 + 4 dup + 16 fma2
            const float* hbase = Hs + (ks + c * 16) * 68;
            const float* wbase = Ws + (ks + c * 16) * 16 + j * 4;
            #pragma unroll
            for (int kk = 0; kk < 16; ++kk) {
                ulonglong2 hA = *(const ulonglong2*)(hbase + kk * 68 + 4 * mg);
                ulonglong2 hB = *(const ulonglong2*)(hbase + kk * 68 + 32 + 4 * mg);
                float4 wv = *(const float4*)(wbase + kk * 16);
                ull w0 = dup2(wv.x), w1 = dup2(wv.y), w2 = dup2(wv.z), w3 = dup2(wv.w);
                fma2(acc[0][0], hA.x, w0); fma2(acc[1][0], hA.y, w0);
                fma2(acc[2][0], hB.x, w0); fma2(acc[3][0], hB.y, w0);
                fma2(acc[0][1], hA.x, w1); fma2(acc[1][1], hA.y, w1);
                fma2(acc[2][1], hB.x, w1); fma2(acc[3][1], hB.y, w1);
                fma2(acc[0][2], hA.x, w2); fma2(acc[1][2], hA.y, w2);
                fma2(acc[2][2], hB.x, w2); fma2(acc[3][2], hB.y, w2);
                fma2(acc[0][3], hA.x, w3); fma2(acc[1][3], hA.y, w3);
                fma2(acc[2][3], hB.x, w3); fma2(acc[3][3], hB.y, w3);
            }
        }

        // write partials: acc[p][q] covers m-pair (m0, m0+1), m0 = (p&1)*2 + (p>>1)*32 + 4*mg
        #pragma unroll
        for (int p = 0; p < 4; ++p) {
            int m0 = ((p & 1) << 1) + ((p >> 1) << 5) + 4 * mg;
            #pragma unroll
            for (int q = 0; q < 4; ++q) {
                float2 s = unp(acc[p][q]);
                part[w * 1088 + m0 * 17 + q * 4 + j]       = s.x;
                part[w * 1088 + (m0 + 1) * 17 + q * 4 + j] = s.y;
            }
        }
        __syncthreads();

        // reduce over warps + fused cell
        float gq0 = 0.f, gq1 = 0.f, gq2 = 0.f, gq3 = 0.f;
        #pragma unroll
        for (int ww = 0; ww < 8; ++ww) {
            const float* pp = part + ww * 1088 + cm * 17 + cjj;
            gq0 += pp[0]; gq1 += pp[4]; gq2 += pp[8]; gq3 += pp[12];
        }
        float gi_ = sigf (gq0 + x0);
        float gf_ = sigf (gq1 + x1);
        float gz_ = tanhf(gq2 + x2);
        float go_ = sigf (gq3 + x3);
        creg = gf_ * creg + gi_ * gz_;
        float h = go_ * tanhf(creg);

        if (seq) seq[((size_t)t * BB + cm) * HH + col] = h;           // fp32 for GEMM2 (layer0)
        h16[(size_t)t * HH * BB + (size_t)col * BB + cm] = __float2half(h);  // [t][k][m], coalesced
        if (finalout && t == TT - 1) finalout[cm * HH + col] = h;

        // grid barrier (release/acquire; no L1 flush)
        if (t < TT - 1) {
            __syncthreads();
            if (tid == 0) st_release(&flags[blk * 8], (unsigned)(t + 1));
            if (tid < NBLK) {
                while (ld_acquire(&flags[tid * 8]) < (unsigned)(t + 1)) __nanosleep(32);
            }
            __syncthreads();
        }
    }
}

// ---------------- launch ----------------
extern "C" void kernel_launch(void* const* d_in, const int* in_sizes, int n_in,
                              void* d_out, int out_size) {
    const float* x    = (const float*)d_in[0];
    const float* Wih0 = (const float*)d_in[1];
    const float* Whh0 = (const float*)d_in[2];
    const float* bih0 = (const float*)d_in[3];
    const float* bhh0 = (const float*)d_in[4];
    const float* Wih1 = (const float*)d_in[5];
    const float* Whh1 = (const float*)d_in[6];
    const float* bih1 = (const float*)d_in[7];
    const float* bhh1 = (const float*)d_in[8];
    float* out = (float*)d_out;

    float *xTt, *xg, *seq;
    __half *h16, *z16;
    unsigned* flags;
    cudaGetSymbolAddress((void**)&xTt,  g_xTt);
    cudaGetSymbolAddress((void**)&xg,   g_xg);
    cudaGetSymbolAddress((void**)&seq,  g_seq);
    cudaGetSymbolAddress((void**)&h16,  g_h16);
    cudaGetSymbolAddress((void**)&z16,  g_z16);
    cudaGetSymbolAddress((void**)&flags, g_flag);

    const int smem = (512 * 68 + 512 * 16 + 8 * 64 * 17) * 4;
    cudaFuncSetAttribute(lstm_rec, cudaFuncAttributeMaxDynamicSharedMemorySize, smem);

    reset_kernel<<<1, 256>>>();

    dim3 tb(32, 8), tg(TT / 32, FF / 32, BB);
    transpose_x_kernel<<<tg, tb>>>(x);

    gemm_gates<FF><<<dim3(GG / 128, TT * BB / 128), 256>>>(xTt, Wih0, bih0, bhh0, xg);
    lstm_rec<<<NBLK, 256, smem>>>(xg, z16, Whh0, seq, h16, nullptr, flags);
    gemm_gates<HH><<<dim3(GG / 128, TT * BB / 128), 256>>>(seq, Wih1, bih1, bhh1, xg);
    lstm_rec<<<NBLK, 256, smem>>>(xg, z16, Whh1, nullptr, h16, out, flags + NBLK * 8);
}